// round 1
// baseline (speedup 1.0000x reference)
#include <cuda_runtime.h>
#include <math.h>

#define Bq   2
#define Nn   2048
#define Dd   256
#define Hh   4
#define DHd  64
#define Jj   32
#define FFf  4
#define Mm   16
#define EINe 137
#define HIDh 274
#define QKVC (3*Hh*DHd)   // 768
#define NODES (Bq*Hh*Nn)  // 16384

// ---------------- scratch (device globals; no allocation allowed) ----------------
__device__ float g_qkv [Bq*Nn*QKVC];     // (b*N+n, 768): q|k|v
__device__ float g_sim [NODES*Jj];
__device__ float g_cw  [NODES*Jj];
__device__ float g_outh[Bq*Nn*Dd];       // (b,n, h*64+d)

// ---------------- generic 64x64 tiled SGEMM, C = A@B (+bias) ----------------
__global__ void gemm_tile(const float* __restrict__ A, const float* __restrict__ Bm,
                          const float* __restrict__ bias, float* __restrict__ C,
                          int M, int N, int K)
{
    __shared__ float As[16][65];
    __shared__ float Bs[16][65];
    int tid = threadIdx.x;
    int tx = tid & 15, ty = tid >> 4;
    int rowBase = blockIdx.y * 64;
    int colBase = blockIdx.x * 64;
    float acc[4][4] = {};
    for (int k0 = 0; k0 < K; k0 += 16) {
        for (int i = tid; i < 1024; i += 256) {
            int r = i >> 4, kk = i & 15;
            As[kk][r] = A[(long)(rowBase + r) * K + k0 + kk];
        }
        for (int i = tid; i < 1024; i += 256) {
            int kk = i >> 6, c = i & 63;
            Bs[kk][c] = Bm[(long)(k0 + kk) * N + colBase + c];
        }
        __syncthreads();
        #pragma unroll
        for (int kk = 0; kk < 16; kk++) {
            float a[4], bb[4];
            #pragma unroll
            for (int r = 0; r < 4; r++) a[r] = As[kk][ty*4 + r];
            #pragma unroll
            for (int c = 0; c < 4; c++) bb[c] = Bs[kk][tx*4 + c];
            #pragma unroll
            for (int r = 0; r < 4; r++)
                #pragma unroll
                for (int c = 0; c < 4; c++)
                    acc[r][c] += a[r] * bb[c];
        }
        __syncthreads();
    }
    #pragma unroll
    for (int r = 0; r < 4; r++) {
        int row = rowBase + ty*4 + r;
        #pragma unroll
        for (int c = 0; c < 4; c++) {
            int col = colBase + tx*4 + c;
            float v = acc[r][c];
            if (bias) v += bias[col];
            C[(long)row * N + col] = v;
        }
    }
}

// ---------------- fused edge MLP: w_e1/w_e2 resident in SMEM ----------------
// block = 256 threads, loops over nodesPerBlock (b,h,n) nodes.
// per node: build E[32][137], layer1 -> H[32][274] (relu), layer2 -> m[32][16] (relu),
// then a/c branch MLPs -> sim, coor_weight per edge.
__global__ void __launch_bounds__(256, 1)
edge_kernel(const float* __restrict__ qkv, const float* __restrict__ coors,
            const int* __restrict__ nbhd,
            const float* __restrict__ w_e1, const float* __restrict__ b_e1,
            const float* __restrict__ w_e2, const float* __restrict__ b_e2,
            const float* __restrict__ w_a1, const float* __restrict__ b_a1,
            const float* __restrict__ w_a2, const float* __restrict__ b_a2,
            const float* __restrict__ w_c1, const float* __restrict__ b_c1,
            const float* __restrict__ w_c2, const float* __restrict__ b_c2,
            float* __restrict__ simo, float* __restrict__ cwo,
            int nodesPerBlock)
{
    extern __shared__ float sm[];
    float* sW1 = sm;                          // 137*274 + 32 pad (overread safety)
    float* sW2 = sW1 + EINe*HIDh + 32;        // 274*16
    float* sE  = sW2 + HIDh*Mm;               // 32*137
    float* sH  = sE  + Jj*EINe;               // 32*274
    float* sM  = sH  + Jj*HIDh;               // 32*16

    int tid = threadIdx.x;
    for (int i = tid; i < EINe*HIDh; i += 256) sW1[i] = w_e1[i];
    for (int i = tid; i < HIDh*Mm;  i += 256) sW2[i] = w_e2[i];
    if (tid < 32) sW1[EINe*HIDh + tid] = 0.f;
    __syncthreads();

    int tx = tid & 31, ty = tid >> 5;        // layer1 mapping: tx = hidden lane, ty = j-group
    int nodeBase = blockIdx.x * nodesPerBlock;

    for (int it = 0; it < nodesPerBlock; it++) {
        int node = nodeBase + it;
        int b = node / (Hh*Nn);
        int h = (node / Nn) % Hh;
        int n = node % Nn;
        long qrow = (long)(b*Nn + n) * QKVC;

        // ---- build edge inputs E[j][0:64]=q, [64:128]=k_nb, [128:137]=rel_enc ----
        {
            int j  = tid >> 3;
            int t8 = tid & 7;
            int idx = nbhd[(b*Nn + n)*Jj + j];
            long krow = (long)(b*Nn + idx) * QKVC;
            #pragma unroll
            for (int d = t8; d < DHd; d += 8) {
                sE[j*EINe + d]       = qkv[qrow + h*DHd + d];
                sE[j*EINe + DHd + d] = qkv[krow + Hh*DHd + h*DHd + d];
            }
            if (t8 == 0) {
                float dx = coors[(b*Nn+n)*3+0] - coors[(b*Nn+idx)*3+0];
                float dy = coors[(b*Nn+n)*3+1] - coors[(b*Nn+idx)*3+1];
                float dz = coors[(b*Nn+n)*3+2] - coors[(b*Nn+idx)*3+2];
                float x = dx*dx + dy*dy + dz*dz;
                #pragma unroll
                for (int f = 0; f < FFf; f++) {
                    float xs = x / (float)(1 << f);
                    sE[j*EINe + 2*DHd + f]       = sinf(xs);
                    sE[j*EINe + 2*DHd + FFf + f] = cosf(xs);
                }
                sE[j*EINe + 2*DHd + 2*FFf] = x;
            }
        }
        __syncthreads();

        // ---- layer 1: H[32][274] = relu(E @ W1 + b1); thread tile 4j x 9o ----
        {
            float acc[4][9];
            #pragma unroll
            for (int r = 0; r < 4; r++)
                #pragma unroll
                for (int oc = 0; oc < 9; oc++) acc[r][oc] = 0.f;

            const float* e0p = &sE[(ty*4+0)*EINe];
            const float* e1p = &sE[(ty*4+1)*EINe];
            const float* e2p = &sE[(ty*4+2)*EINe];
            const float* e3p = &sE[(ty*4+3)*EINe];
            #pragma unroll 2
            for (int i = 0; i < EINe; i++) {
                float e0 = e0p[i], e1 = e1p[i], e2 = e2p[i], e3 = e3p[i];
                const float* wrow = &sW1[i*HIDh + tx];
                #pragma unroll
                for (int oc = 0; oc < 9; oc++) {
                    float w = wrow[oc*32];
                    acc[0][oc] += e0 * w;
                    acc[1][oc] += e1 * w;
                    acc[2][oc] += e2 * w;
                    acc[3][oc] += e3 * w;
                }
            }
            #pragma unroll
            for (int oc = 0; oc < 9; oc++) {
                int o = tx + oc*32;
                if (o < HIDh) {
                    float bb = b_e1[o];
                    #pragma unroll
                    for (int r = 0; r < 4; r++)
                        sH[(ty*4+r)*HIDh + o] = fmaxf(acc[r][oc] + bb, 0.f);
                }
            }
        }
        __syncthreads();

        // ---- layer 2: m[32][16] = relu(H @ W2 + b2) ----
        {
            #pragma unroll
            for (int rep = 0; rep < 2; rep++) {
                int oi = tid + rep*256;
                int j = oi >> 4, t = oi & 15;
                float acc = b_e2[t];
                #pragma unroll 2
                for (int i = 0; i < HIDh; i++)
                    acc += sH[j*HIDh + i] * sW2[i*Mm + t];
                sM[j*Mm + t] = fmaxf(acc, 0.f);
            }
        }
        __syncthreads();

        // ---- a/c branch MLPs: 8 threads per j (2 branches x 4 u-quarters) ----
        {
            int j   = tid >> 3;
            int sub = tid & 7;
            int br  = sub >> 2;       // 0 = attention, 1 = coor
            int uq  = sub & 3;
            const float* w1 = br ? w_c1 : w_a1;
            const float* b1 = br ? b_c1 : b_a1;
            const float* w2 = br ? w_c2 : w_a2;
            float mv[16];
            #pragma unroll
            for (int t = 0; t < 16; t++) mv[t] = sM[j*Mm + t];
            float part = 0.f;
            #pragma unroll
            for (int uu = 0; uu < 16; uu++) {
                int u = uq*16 + uu;
                float hv = b1[u];
                #pragma unroll
                for (int t = 0; t < 16; t++) hv += mv[t] * w1[t*64 + u];
                part += fmaxf(hv, 0.f) * w2[u];
            }
            part += __shfl_down_sync(0xffffffffu, part, 2);
            part += __shfl_down_sync(0xffffffffu, part, 1);
            if (uq == 0) {
                float val = part + (br ? b_c2[0] : b_a2[0]);
                (br ? cwo : simo)[(long)node*Jj + j] = val;
            }
        }
        __syncthreads();
    }
}

// ---------------- softmax over j, out = attn@v_nb, coors_out ----------------
__global__ void attend_kernel(const float* __restrict__ qkv,
                              const float* __restrict__ simi, const float* __restrict__ cwi,
                              const int* __restrict__ nbhd, const float* __restrict__ basis,
                              float* __restrict__ outh, float* __restrict__ coors_out)
{
    int bn = blockIdx.x;
    int b = bn / Nn, n = bn % Nn;
    int w = threadIdx.x >> 5, lane = threadIdx.x & 31;
    int idx = nbhd[bn*Jj + lane];

    float s = simi[((long)((b*Hh + w)*Nn + n))*Jj + lane];
    float mx = s;
    #pragma unroll
    for (int o = 16; o; o >>= 1) mx = fmaxf(mx, __shfl_xor_sync(0xffffffffu, mx, o));
    float e = expf(s - mx);
    float sum = e;
    #pragma unroll
    for (int o = 16; o; o >>= 1) sum += __shfl_xor_sync(0xffffffffu, sum, o);
    float attn = e / sum;

    float acc0 = 0.f, acc1 = 0.f;
    #pragma unroll
    for (int j = 0; j < Jj; j++) {
        float a = __shfl_sync(0xffffffffu, attn, j);
        int ij  = __shfl_sync(0xffffffffu, idx,  j);
        const float* vr = qkv + (long)(b*Nn + ij)*QKVC + 2*Hh*DHd + w*DHd;
        acc0 += a * vr[lane];
        acc1 += a * vr[lane + 32];
    }
    outh[(long)bn*Dd + w*DHd + lane]      = acc0;
    outh[(long)bn*Dd + w*DHd + lane + 32] = acc1;

    if (w == 0) {
        float cwt = 0.f;
        #pragma unroll
        for (int hh = 0; hh < Hh; hh++)
            cwt += cwi[((long)((b*Hh + hh)*Nn + n))*Jj + lane];
        const float* brow = basis + ((long)(b*Nn + n)*Nn + idx)*3;
        float cx = cwt*brow[0], cy = cwt*brow[1], cz = cwt*brow[2];
        #pragma unroll
        for (int o = 16; o; o >>= 1) {
            cx += __shfl_xor_sync(0xffffffffu, cx, o);
            cy += __shfl_xor_sync(0xffffffffu, cy, o);
            cz += __shfl_xor_sync(0xffffffffu, cz, o);
        }
        if (lane == 0) {
            coors_out[bn*3+0] = cx;
            coors_out[bn*3+1] = cy;
            coors_out[bn*3+2] = cz;
        }
    }
}

// ---------------- launch ----------------
extern "C" void kernel_launch(void* const* d_in, const int* in_sizes, int n_in,
                              void* d_out, int out_size)
{
    const float* feats  = (const float*)d_in[0];
    const float* coors  = (const float*)d_in[1];
    const float* basis  = (const float*)d_in[2];
    const int*   nbhd   = (const int*)  d_in[3];
    const float* w_qkv  = (const float*)d_in[4];
    const float* w_out  = (const float*)d_in[5];
    const float* b_out  = (const float*)d_in[6];
    const float* w_e1   = (const float*)d_in[7];
    const float* b_e1   = (const float*)d_in[8];
    const float* w_e2   = (const float*)d_in[9];
    const float* b_e2   = (const float*)d_in[10];
    const float* w_a1   = (const float*)d_in[11];
    const float* b_a1   = (const float*)d_in[12];
    const float* w_a2   = (const float*)d_in[13];
    const float* b_a2   = (const float*)d_in[14];
    const float* w_c1   = (const float*)d_in[15];
    const float* b_c1   = (const float*)d_in[16];
    const float* w_c2   = (const float*)d_in[17];
    const float* b_c2   = (const float*)d_in[18];

    float* out       = (float*)d_out;            // (B,N,D)
    float* coors_out = out + (long)Bq*Nn*Dd;     // (B,N,3)

    void* p;
    cudaGetSymbolAddress(&p, g_qkv);  float* qkv  = (float*)p;
    cudaGetSymbolAddress(&p, g_sim);  float* simv = (float*)p;
    cudaGetSymbolAddress(&p, g_cw);   float* cwv  = (float*)p;
    cudaGetSymbolAddress(&p, g_outh); float* outh = (float*)p;

    // 1) qkv = feats @ w_qkv : (4096x256)@(256x768)
    gemm_tile<<<dim3(QKVC/64, (Bq*Nn)/64), 256>>>(feats, w_qkv, nullptr, qkv,
                                                  Bq*Nn, QKVC, Dd);

    // 2) fused edge MLP
    const int smemBytes = (EINe*HIDh + 32 + HIDh*Mm + Jj*EINe + Jj*HIDh + Jj*Mm) * 4;
    cudaFuncSetAttribute(edge_kernel, cudaFuncAttributeMaxDynamicSharedMemorySize, smemBytes);
    const int nodesPerBlock = 8;
    edge_kernel<<<NODES/nodesPerBlock, 256, smemBytes>>>(
        qkv, coors, nbhd,
        w_e1, b_e1, w_e2, b_e2,
        w_a1, b_a1, w_a2, b_a2,
        w_c1, b_c1, w_c2, b_c2,
        simv, cwv, nodesPerBlock);

    // 3) softmax + v-gather + coors einsum
    attend_kernel<<<Bq*Nn, 128>>>(qkv, simv, cwv, nbhd, basis, outh, coors_out);

    // 4) out = outh @ w_out + b_out : (4096x256)@(256x256)
    gemm_tile<<<dim3(Dd/64, (Bq*Nn)/64), 256>>>(outh, w_out, b_out, out,
                                                Bq*Nn, Dd, Dd);
}

// round 2
// speedup vs baseline: 1.9918x; 1.9918x over previous
#include <cuda_runtime.h>
#include <math.h>

#define Bq   2
#define Nn   2048
#define Dd   256
#define Hh   4
#define DHd  64
#define Jj   32
#define FFf  4
#define Mm   16
#define EINe 137
#define HIDh 274
#define HIDP 276            // padded hidden dim (zeros in cols 274,275)
#define QKVC (3*Hh*DHd)     // 768
#define NODES (Bq*Nn)       // 4096 (b,n) nodes
#define RS   280            // sR1 row stride (mult of 4)
#define HS   277            // sH row stride (odd -> conflict-free column reads)

// ---------------- scratch ----------------
__device__ float g_qkv [Bq*Nn*QKVC];
__device__ float g_q1  [Bq*Nn*Hh*HIDP];
__device__ float g_k1  [Bq*Nn*Hh*HIDP];
__device__ float g_sim [Bq*Hh*Nn*Jj];
__device__ float g_cw  [Bq*Hh*Nn*Jj];
__device__ float g_outh[Bq*Nn*Dd];

// ---------------- generic 64x64 tiled SGEMM, C = A@B (+bias) ----------------
__global__ void gemm_tile(const float* __restrict__ A, const float* __restrict__ Bm,
                          const float* __restrict__ bias, float* __restrict__ C,
                          int M, int N, int K)
{
    __shared__ float As[16][65];
    __shared__ float Bs[16][65];
    int tid = threadIdx.x;
    int tx = tid & 15, ty = tid >> 4;
    int rowBase = blockIdx.y * 64;
    int colBase = blockIdx.x * 64;
    float acc[4][4] = {};
    for (int k0 = 0; k0 < K; k0 += 16) {
        for (int i = tid; i < 1024; i += 256) {
            int r = i >> 4, kk = i & 15;
            As[kk][r] = A[(long)(rowBase + r) * K + k0 + kk];
        }
        for (int i = tid; i < 1024; i += 256) {
            int kk = i >> 6, c = i & 63;
            Bs[kk][c] = Bm[(long)(k0 + kk) * N + colBase + c];
        }
        __syncthreads();
        #pragma unroll
        for (int kk = 0; kk < 16; kk++) {
            float a[4], bb[4];
            #pragma unroll
            for (int r = 0; r < 4; r++) a[r] = As[kk][ty*4 + r];
            #pragma unroll
            for (int c = 0; c < 4; c++) bb[c] = Bs[kk][tx*4 + c];
            #pragma unroll
            for (int r = 0; r < 4; r++)
                #pragma unroll
                for (int c = 0; c < 4; c++)
                    acc[r][c] += a[r] * bb[c];
        }
        __syncthreads();
    }
    #pragma unroll
    for (int r = 0; r < 4; r++) {
        int row = rowBase + ty*4 + r;
        #pragma unroll
        for (int c = 0; c < 4; c++) {
            int col = colBase + tx*4 + c;
            float v = acc[r][c];
            if (bias) v += bias[col];
            C[(long)row * N + col] = v;
        }
    }
}

// ---------------- q1/k1 precompute: row (node*4+h) = q_h(node) @ W1q ----------------
// grid 256, block 256; each block: 16 nodes -> 64 rows of q1 and k1.
__global__ void __launch_bounds__(256,1) qk1_kernel(
    const float* __restrict__ qkv, const float* __restrict__ w_e1,
    float* __restrict__ q1, float* __restrict__ k1)
{
    extern __shared__ float sm[];
    float* sWq = sm;             // [64][HIDP]
    float* sWk = sWq + 64*HIDP;  // [64][HIDP]
    float* sAq = sWk + 64*HIDP;  // [16][256]
    float* sAk = sAq + 16*256;   // [16][256]
    int tid = threadIdx.x;
    int node0 = blockIdx.x * 16;

    for (int i = tid; i < 64*HIDP; i += 256) {
        int r = i / HIDP, o = i - r*HIDP;
        sWq[i] = (o < HIDh) ? w_e1[r*HIDh + o] : 0.f;
        sWk[i] = (o < HIDh) ? w_e1[(64 + r)*HIDh + o] : 0.f;
    }
    for (int i = tid; i < 4096; i += 256) {
        int t = i >> 8, c = i & 255;
        sAq[i] = qkv[(long)(node0 + t)*QKVC + c];
        sAk[i] = qkv[(long)(node0 + t)*QKVC + 256 + c];
    }
    __syncthreads();

    int ty = tid >> 4, tx = tid & 15;
    for (int pass = 0; pass < 2; pass++) {
        const float* A = pass ? sAk : sAq;
        const float* W = pass ? sWk : sWq;
        float* Cg = pass ? k1 : q1;
        float acc[4][18];
        #pragma unroll
        for (int r = 0; r < 4; r++)
            #pragma unroll
            for (int c = 0; c < 18; c++) acc[r][c] = 0.f;
        #pragma unroll 4
        for (int i = 0; i < 64; i++) {
            float a[4];
            #pragma unroll
            for (int r = 0; r < 4; r++) a[r] = A[ty*256 + r*64 + i];
            #pragma unroll
            for (int c = 0; c < 18; c++) {
                int o = tx + 16*c;
                float w = (o < HIDP) ? W[i*HIDP + o] : 0.f;
                #pragma unroll
                for (int r = 0; r < 4; r++) acc[r][c] += a[r] * w;
            }
        }
        #pragma unroll
        for (int r = 0; r < 4; r++) {
            long grow = (long)(node0 + ty)*4 + r;
            #pragma unroll
            for (int c = 0; c < 18; c++) {
                int o = tx + 16*c;
                if (o < HIDP) Cg[grow*HIDP + o] = acc[r][c];
            }
        }
    }
}

// ---------------- edge kernel v2: factorized layer1 + fused layer2/branches ----------------
// grid = 4096 (one (b,n) node), block = 256.
__global__ void __launch_bounds__(256,1) edge2_kernel(
    const float* __restrict__ q1, const float* __restrict__ k1,
    const float* __restrict__ coors, const int* __restrict__ nbhd,
    const float* __restrict__ w_e1, const float* __restrict__ b_e1,
    const float* __restrict__ w_e2, const float* __restrict__ b_e2,
    const float* __restrict__ w_a1, const float* __restrict__ b_a1,
    const float* __restrict__ w_a2, const float* __restrict__ b_a2,
    const float* __restrict__ w_c1, const float* __restrict__ b_c1,
    const float* __restrict__ w_c2, const float* __restrict__ b_c2,
    float* __restrict__ simo, float* __restrict__ cwo)
{
    extern __shared__ float sm[];
    float* sW2 = sm;                     // [HIDP][16]
    float* sWr = sW2 + HIDP*16;          // [9][HIDP]
    float* sA1 = sWr + 9*HIDP;           // [16][64]
    float* sC1 = sA1 + 16*64;            // [16][64]
    float* sA2 = sC1 + 16*64;            // [64]
    float* sC2 = sA2 + 64;               // [64]
    float* sB1 = sC2 + 64;               // [HIDP]
    float* sB2 = sB1 + HIDP;             // [16]
    float* sBa = sB2 + 16;               // [64]
    float* sBc = sBa + 64;               // [64]
    float* sQB = sBc + 64;               // [HIDP]
    float* sRE = sQB + HIDP;             // [32][12]
    float* sR1 = sRE + 32*12;            // [32][RS]
    float* sH  = sR1 + 32*RS;            // [32][HS]
    float* sMm = sH  + 32*HS;            // [32][16]
    float* sPart = sMm + 32*16;          // [4][512] layout [w][t*32+j]
    float* sScal = sPart + 4*512;        // [2]: b_a2, b_c2
    int*   sIdx  = (int*)(sScal + 4);    // [32]

    int tid = threadIdx.x;
    int bn = blockIdx.x;
    int bB = bn >> 11;       // / Nn
    int nn = bn & (Nn - 1);

    // ---- cooperative weight/bias loads ----
    for (int i = tid; i < HIDP*16; i += 256) {
        int r = i >> 4, t = i & 15;
        sW2[i] = (r < HIDh) ? w_e2[r*16 + t] : 0.f;
    }
    for (int i = tid; i < 9*HIDP; i += 256) {
        int f = i / HIDP, o = i - f*HIDP;
        sWr[i] = (o < HIDh) ? w_e1[(128 + f)*HIDh + o] : 0.f;
    }
    for (int i = tid; i < 1024; i += 256) { sA1[i] = w_a1[i]; sC1[i] = w_c1[i]; }
    if (tid < 64) { sA2[tid] = w_a2[tid]; sC2[tid] = w_c2[tid];
                    sBa[tid] = b_a1[tid]; sBc[tid] = b_c1[tid]; }
    for (int i = tid; i < HIDP; i += 256) sB1[i] = (i < HIDh) ? b_e1[i] : 0.f;
    if (tid < 16) sB2[tid] = b_e2[tid];
    if (tid == 0) { sScal[0] = b_a2[0]; sScal[1] = b_c2[0]; }
    if (tid < 32) sIdx[tid] = nbhd[bn*Jj + tid];
    __syncthreads();

    // ---- rel_enc ----
    if (tid < 32) {
        int j = tid, idx = sIdx[j];
        float dx = coors[bn*3+0] - coors[(bB*Nn+idx)*3+0];
        float dy = coors[bn*3+1] - coors[(bB*Nn+idx)*3+1];
        float dz = coors[bn*3+2] - coors[(bB*Nn+idx)*3+2];
        float x = dx*dx + dy*dy + dz*dz;
        #pragma unroll
        for (int f = 0; f < FFf; f++) {
            float xs = x / (float)(1 << f);
            sRE[j*12 + f]       = sinf(xs);
            sRE[j*12 + FFf + f] = cosf(xs);
        }
        sRE[j*12 + 2*FFf] = x;
    }
    __syncthreads();

    // ---- r1[j][o] = b1[o] + sum_f RE[j][f]*Wr[f][o] ----
    {
        int j = tid >> 3, s = tid & 7;
        float re[9];
        #pragma unroll
        for (int f = 0; f < 9; f++) re[f] = sRE[j*12 + f];
        for (int o4 = s; o4 < 69; o4 += 8) {
            float4 acc = *(float4*)&sB1[o4*4];
            #pragma unroll
            for (int f = 0; f < 9; f++) {
                float4 w = *(float4*)&sWr[f*HIDP + o4*4];
                acc.x += re[f]*w.x; acc.y += re[f]*w.y;
                acc.z += re[f]*w.z; acc.w += re[f]*w.w;
            }
            *(float4*)&sR1[j*RS + o4*4] = acc;
        }
    }
    __syncthreads();

    // ---- per-head: assemble H, layer2, branches ----
    for (int h = 0; h < Hh; h++) {
        // q1 row + broadcast bias lives in q1 table; just stage it
        for (int i = tid; i < HIDP; i += 256)
            sQB[i] = q1[((long)bn*4 + h)*HIDP + i];
        __syncthreads();

        // H[j][i] = relu(qb[i] + k1[idx_j,h][i] + r1[j][i])
        {
            int w = tid >> 5, lane = tid & 31;
            #pragma unroll
            for (int jj = 0; jj < 4; jj++) {
                int j = w + 8*jj;
                long krow = ((long)(bB*Nn + sIdx[j])*4 + h) * HIDP;
                for (int o4 = lane; o4 < 69; o4 += 32) {
                    float4 k4 = *(const float4*)&k1[krow + o4*4];
                    float4 q4 = *(float4*)&sQB[o4*4];
                    float4 r4 = *(float4*)&sR1[j*RS + o4*4];
                    int base = j*HS + o4*4;
                    sH[base+0] = fmaxf(k4.x + q4.x + r4.x, 0.f);
                    sH[base+1] = fmaxf(k4.y + q4.y + r4.y, 0.f);
                    sH[base+2] = fmaxf(k4.z + q4.z + r4.z, 0.f);
                    sH[base+3] = fmaxf(k4.w + q4.w + r4.w, 0.f);
                }
            }
        }
        __syncthreads();

        // layer2: warps 0..3, i-slices of 69; thread tile 4j x 4t
        if (tid < 128) {
            int w = tid >> 5, lane = tid & 31;
            int jg = lane >> 2, tg = lane & 3;
            float acc[4][4] = {};
            int i0 = w*69;
            #pragma unroll 3
            for (int ii = 0; ii < 69; ii++) {
                int i = i0 + ii;
                float4 w4 = *(float4*)&sW2[i*16 + tg*4];
                float hv0 = sH[(jg*4+0)*HS + i];
                float hv1 = sH[(jg*4+1)*HS + i];
                float hv2 = sH[(jg*4+2)*HS + i];
                float hv3 = sH[(jg*4+3)*HS + i];
                acc[0][0] += hv0*w4.x; acc[0][1] += hv0*w4.y; acc[0][2] += hv0*w4.z; acc[0][3] += hv0*w4.w;
                acc[1][0] += hv1*w4.x; acc[1][1] += hv1*w4.y; acc[1][2] += hv1*w4.z; acc[1][3] += hv1*w4.w;
                acc[2][0] += hv2*w4.x; acc[2][1] += hv2*w4.y; acc[2][2] += hv2*w4.z; acc[2][3] += hv2*w4.w;
                acc[3][0] += hv3*w4.x; acc[3][1] += hv3*w4.y; acc[3][2] += hv3*w4.z; acc[3][3] += hv3*w4.w;
            }
            #pragma unroll
            for (int r = 0; r < 4; r++)
                #pragma unroll
                for (int c = 0; c < 4; c++)
                    sPart[w*512 + (tg*4+c)*32 + (jg*4+r)] = acc[r][c];
        }
        __syncthreads();

        // combine partials -> m[j][t] = relu(. + b2)
        for (int oi = tid; oi < 512; oi += 256) {
            int j = oi & 31, t = oi >> 5;
            float v = sB2[t] + sPart[oi] + sPart[512+oi] + sPart[1024+oi] + sPart[1536+oi];
            sMm[j*16 + t] = fmaxf(v, 0.f);
        }
        __syncthreads();

        // branches: thread = (j, br, u-half). 128 threads.
        if (tid < 128) {
            int j = tid >> 2, sub = tid & 3, br = sub >> 1, uh = sub & 1;
            const float* w1 = br ? sC1 : sA1;
            const float* w2 = br ? sC2 : sA2;
            const float* bb = br ? sBc : sBa;
            float mv[16];
            #pragma unroll
            for (int t = 0; t < 16; t++) mv[t] = sMm[j*16 + t];
            float acc = 0.f;
            #pragma unroll
            for (int u4 = 0; u4 < 8; u4++) {
                int u = uh*8 + u4;
                float4 hv = *(float4*)&bb[u*4];
                #pragma unroll
                for (int t = 0; t < 16; t++) {
                    float4 w = *(float4*)&w1[t*64 + u*4];
                    hv.x += mv[t]*w.x; hv.y += mv[t]*w.y;
                    hv.z += mv[t]*w.z; hv.w += mv[t]*w.w;
                }
                float4 w2v = *(float4*)&w2[u*4];
                acc += fmaxf(hv.x,0.f)*w2v.x + fmaxf(hv.y,0.f)*w2v.y
                     + fmaxf(hv.z,0.f)*w2v.z + fmaxf(hv.w,0.f)*w2v.w;
            }
            acc += __shfl_xor_sync(0xffffffffu, acc, 1);
            if (uh == 0) {
                long e = ((long)(bB*Hh + h)*Nn + nn)*Jj + j;
                float val = acc + (br ? sScal[1] : sScal[0]);
                (br ? cwo : simo)[e] = val;
            }
        }
        __syncthreads();
    }
}

// ---------------- softmax over j, out = attn@v_nb, coors_out ----------------
__global__ void attend_kernel(const float* __restrict__ qkv,
                              const float* __restrict__ simi, const float* __restrict__ cwi,
                              const int* __restrict__ nbhd, const float* __restrict__ basis,
                              float* __restrict__ outh, float* __restrict__ coors_out)
{
    int bn = blockIdx.x;
    int b = bn / Nn, n = bn % Nn;
    int w = threadIdx.x >> 5, lane = threadIdx.x & 31;
    int idx = nbhd[bn*Jj + lane];

    float s = simi[((long)((b*Hh + w)*Nn + n))*Jj + lane];
    float mx = s;
    #pragma unroll
    for (int o = 16; o; o >>= 1) mx = fmaxf(mx, __shfl_xor_sync(0xffffffffu, mx, o));
    float e = expf(s - mx);
    float sum = e;
    #pragma unroll
    for (int o = 16; o; o >>= 1) sum += __shfl_xor_sync(0xffffffffu, sum, o);
    float attn = e / sum;

    float acc0 = 0.f, acc1 = 0.f;
    #pragma unroll
    for (int j = 0; j < Jj; j++) {
        float a = __shfl_sync(0xffffffffu, attn, j);
        int ij  = __shfl_sync(0xffffffffu, idx,  j);
        const float* vr = qkv + (long)(b*Nn + ij)*QKVC + 2*Hh*DHd + w*DHd;
        acc0 += a * vr[lane];
        acc1 += a * vr[lane + 32];
    }
    outh[(long)bn*Dd + w*DHd + lane]      = acc0;
    outh[(long)bn*Dd + w*DHd + lane + 32] = acc1;

    if (w == 0) {
        float cwt = 0.f;
        #pragma unroll
        for (int hh = 0; hh < Hh; hh++)
            cwt += cwi[((long)((b*Hh + hh)*Nn + n))*Jj + lane];
        const float* brow = basis + ((long)(b*Nn + n)*Nn + idx)*3;
        float cx = cwt*brow[0], cy = cwt*brow[1], cz = cwt*brow[2];
        #pragma unroll
        for (int o = 16; o; o >>= 1) {
            cx += __shfl_xor_sync(0xffffffffu, cx, o);
            cy += __shfl_xor_sync(0xffffffffu, cy, o);
            cz += __shfl_xor_sync(0xffffffffu, cz, o);
        }
        if (lane == 0) {
            coors_out[bn*3+0] = cx;
            coors_out[bn*3+1] = cy;
            coors_out[bn*3+2] = cz;
        }
    }
}

// ---------------- launch ----------------
extern "C" void kernel_launch(void* const* d_in, const int* in_sizes, int n_in,
                              void* d_out, int out_size)
{
    const float* feats  = (const float*)d_in[0];
    const float* coors  = (const float*)d_in[1];
    const float* basis  = (const float*)d_in[2];
    const int*   nbhd   = (const int*)  d_in[3];
    const float* w_qkv  = (const float*)d_in[4];
    const float* w_out  = (const float*)d_in[5];
    const float* b_out  = (const float*)d_in[6];
    const float* w_e1   = (const float*)d_in[7];
    const float* b_e1   = (const float*)d_in[8];
    const float* w_e2   = (const float*)d_in[9];
    const float* b_e2   = (const float*)d_in[10];
    const float* w_a1   = (const float*)d_in[11];
    const float* b_a1   = (const float*)d_in[12];
    const float* w_a2   = (const float*)d_in[13];
    const float* b_a2   = (const float*)d_in[14];
    const float* w_c1   = (const float*)d_in[15];
    const float* b_c1   = (const float*)d_in[16];
    const float* w_c2   = (const float*)d_in[17];
    const float* b_c2   = (const float*)d_in[18];

    float* out       = (float*)d_out;
    float* coors_out = out + (long)Bq*Nn*Dd;

    void* p;
    cudaGetSymbolAddress(&p, g_qkv);  float* qkv  = (float*)p;
    cudaGetSymbolAddress(&p, g_q1);   float* q1   = (float*)p;
    cudaGetSymbolAddress(&p, g_k1);   float* k1   = (float*)p;
    cudaGetSymbolAddress(&p, g_sim);  float* simv = (float*)p;
    cudaGetSymbolAddress(&p, g_cw);   float* cwv  = (float*)p;
    cudaGetSymbolAddress(&p, g_outh); float* outh = (float*)p;

    // 1) qkv = feats @ w_qkv
    gemm_tile<<<dim3(QKVC/64, (Bq*Nn)/64), 256>>>(feats, w_qkv, nullptr, qkv,
                                                  Bq*Nn, QKVC, Dd);

    // 2) q1/k1 tables
    const int smemQK = (64*HIDP*2 + 16*256*2) * 4;
    cudaFuncSetAttribute(qk1_kernel, cudaFuncAttributeMaxDynamicSharedMemorySize, smemQK);
    qk1_kernel<<<256, 256, smemQK>>>(qkv, w_e1, q1, k1);

    // 3) edge kernel v2
    const int smemE = (HIDP*16 + 9*HIDP + 1024 + 1024 + 64 + 64 + HIDP + 16 + 64 + 64
                       + HIDP + 32*12 + 32*RS + 32*HS + 32*16 + 4*512 + 4 + 32) * 4;
    cudaFuncSetAttribute(edge2_kernel, cudaFuncAttributeMaxDynamicSharedMemorySize, smemE);
    edge2_kernel<<<NODES, 256, smemE>>>(q1, k1, coors, nbhd,
        w_e1, b_e1, w_e2, b_e2, w_a1, b_a1, w_a2, b_a2, w_c1, b_c1, w_c2, b_c2,
        simv, cwv);

    // 4) softmax + v-gather + coors einsum
    attend_kernel<<<Bq*Nn, 128>>>(qkv, simv, cwv, nbhd, basis, outh, coors_out);

    // 5) out = outh @ w_out + b_out
    gemm_tile<<<dim3(Dd/64, (Bq*Nn)/64), 256>>>(outh, w_out, b_out, out,
                                                Bq*Nn, Dd, Dd);
}

// round 3
// speedup vs baseline: 5.1564x; 2.5887x over previous
#include <cuda_runtime.h>
#include <math.h>

#define Bq   2
#define Nn   2048
#define Dd   256
#define Hh   4
#define DHd  64
#define Jj   32
#define FFf  4
#define Mm   16
#define HID  274
#define HP   288            // padded hidden dim (cols 274..287 zero)
#define W2S  292            // sW2t row stride (floats)
#define QKVC (3*Hh*DHd)     // 768
#define NODES (Bq*Nn)       // 4096

// ---------------- scratch ----------------
__device__ float g_qkv [Bq*Nn*QKVC];
__device__ float g_q1  [Bq*Nn*Hh*HP];
__device__ float g_k1  [Bq*Nn*Hh*HP];
__device__ float g_sim [Bq*Hh*Nn*Jj];
__device__ float g_cw  [Bq*Hh*Nn*Jj];
__device__ float g_outh[Bq*Nn*Dd];

// ---------------- generic 64x64 tiled SGEMM, C = A@B (+bias) ----------------
__global__ void gemm_tile(const float* __restrict__ A, const float* __restrict__ Bm,
                          const float* __restrict__ bias, float* __restrict__ C,
                          int M, int N, int K)
{
    __shared__ float As[16][65];
    __shared__ float Bs[16][65];
    int tid = threadIdx.x;
    int tx = tid & 15, ty = tid >> 4;
    int rowBase = blockIdx.y * 64;
    int colBase = blockIdx.x * 64;
    float acc[4][4] = {};
    for (int k0 = 0; k0 < K; k0 += 16) {
        for (int i = tid; i < 1024; i += 256) {
            int r = i >> 4, kk = i & 15;
            As[kk][r] = A[(long)(rowBase + r) * K + k0 + kk];
        }
        for (int i = tid; i < 1024; i += 256) {
            int kk = i >> 6, c = i & 63;
            Bs[kk][c] = Bm[(long)(k0 + kk) * N + colBase + c];
        }
        __syncthreads();
        #pragma unroll
        for (int kk = 0; kk < 16; kk++) {
            float a[4], bb[4];
            #pragma unroll
            for (int r = 0; r < 4; r++) a[r] = As[kk][ty*4 + r];
            #pragma unroll
            for (int c = 0; c < 4; c++) bb[c] = Bs[kk][tx*4 + c];
            #pragma unroll
            for (int r = 0; r < 4; r++)
                #pragma unroll
                for (int c = 0; c < 4; c++)
                    acc[r][c] += a[r] * bb[c];
        }
        __syncthreads();
    }
    #pragma unroll
    for (int r = 0; r < 4; r++) {
        int row = rowBase + ty*4 + r;
        #pragma unroll
        for (int c = 0; c < 4; c++) {
            int col = colBase + tx*4 + c;
            float v = acc[r][c];
            if (bias) v += bias[col];
            C[(long)row * N + col] = v;
        }
    }
}

// ---------------- q1/k1 precompute: row (node*4+h) = q_h(node) @ W1q ----------------
__global__ void __launch_bounds__(256,1) qk1_kernel(
    const float* __restrict__ qkv, const float* __restrict__ w_e1,
    float* __restrict__ q1, float* __restrict__ k1)
{
    extern __shared__ float sm[];
    float* sWq = sm;             // [64][HP]
    float* sWk = sWq + 64*HP;    // [64][HP]
    float* sAq = sWk + 64*HP;    // [16][256]
    float* sAk = sAq + 16*256;   // [16][256]
    int tid = threadIdx.x;
    int node0 = blockIdx.x * 16;

    for (int i = tid; i < 64*HP; i += 256) {
        int r = i / HP, o = i - r*HP;
        sWq[i] = (o < HID) ? w_e1[r*HID + o] : 0.f;
        sWk[i] = (o < HID) ? w_e1[(64 + r)*HID + o] : 0.f;
    }
    for (int i = tid; i < 4096; i += 256) {
        int t = i >> 8, c = i & 255;
        sAq[i] = qkv[(long)(node0 + t)*QKVC + c];
        sAk[i] = qkv[(long)(node0 + t)*QKVC + 256 + c];
    }
    __syncthreads();

    int ty = tid >> 4, tx = tid & 15;
    for (int pass = 0; pass < 2; pass++) {
        const float* A = pass ? sAk : sAq;
        const float* W = pass ? sWk : sWq;
        float* Cg = pass ? k1 : q1;
        float acc[4][18];
        #pragma unroll
        for (int r = 0; r < 4; r++)
            #pragma unroll
            for (int c = 0; c < 18; c++) acc[r][c] = 0.f;
        #pragma unroll 4
        for (int i = 0; i < 64; i++) {
            float a[4];
            #pragma unroll
            for (int r = 0; r < 4; r++) a[r] = A[ty*256 + r*64 + i];
            #pragma unroll
            for (int c = 0; c < 18; c++) {
                float w = W[i*HP + tx + 16*c];
                #pragma unroll
                for (int r = 0; r < 4; r++) acc[r][c] += a[r] * w;
            }
        }
        #pragma unroll
        for (int r = 0; r < 4; r++) {
            long grow = (long)(node0 + ty)*4 + r;
            #pragma unroll
            for (int c = 0; c < 18; c++)
                Cg[grow*HP + tx + 16*c] = acc[r][c];
        }
    }
}

// ---------------- edge_flat: warp = (node, j-quad), all 4 heads; no barriers ----------------
__global__ void __launch_bounds__(256) edge_flat(
    const float* __restrict__ q1, const float* __restrict__ k1,
    const float* __restrict__ coors, const int* __restrict__ nbhd,
    const float* __restrict__ w_e1, const float* __restrict__ b_e1,
    const float* __restrict__ w_e2, const float* __restrict__ b_e2,
    const float* __restrict__ w_a1, const float* __restrict__ b_a1,
    const float* __restrict__ w_a2, const float* __restrict__ b_a2,
    const float* __restrict__ w_c1, const float* __restrict__ b_c1,
    const float* __restrict__ w_c2, const float* __restrict__ b_c2,
    float* __restrict__ simo, float* __restrict__ cwo)
{
    extern __shared__ float sm[];
    float* sWr  = sm;               // [9][HP]
    float* sW2t = sWr + 9*HP;       // [16][W2S]  (transposed w_e2)
    float* sB1  = sW2t + 16*W2S;    // [HP]
    float* sQ1  = sB1 + HP;         // [4][HP]
    float* sA1  = sQ1 + 4*HP;       // [16][64]
    float* sC1  = sA1 + 1024;       // [16][64]
    float* sBa  = sC1 + 1024;       // [64]
    float* sBc  = sBa + 64;         // [64]
    float* sA2  = sBc + 64;         // [64]
    float* sC2  = sA2 + 64;         // [64]
    float* sB2  = sC2 + 64;         // [16]
    float* sScal= sB2 + 16;         // [2]
    int*   sIdx = (int*)(sScal + 4);// [32]

    int tid = threadIdx.x;
    int bn  = blockIdx.x;
    int bB  = bn >> 11;
    int nn  = bn & (Nn - 1);

    for (int i = tid; i < 9*HP; i += 256) {
        int f = i / HP, o = i - f*HP;
        sWr[i] = (o < HID) ? w_e1[(128 + f)*HID + o] : 0.f;
    }
    for (int i = tid; i < 16*W2S; i += 256) {
        int t = i / W2S, o = i - t*W2S;
        sW2t[i] = (o < HID) ? w_e2[o*16 + t] : 0.f;
    }
    for (int i = tid; i < HP; i += 256) sB1[i] = (i < HID) ? b_e1[i] : 0.f;
    for (int i = tid; i < 4*HP; i += 256) sQ1[i] = q1[(long)bn*4*HP + i];
    for (int i = tid; i < 1024; i += 256) { sA1[i] = w_a1[i]; sC1[i] = w_c1[i]; }
    if (tid < 64) { sBa[tid] = b_a1[tid]; sBc[tid] = b_c1[tid];
                    sA2[tid] = w_a2[tid]; sC2[tid] = w_c2[tid]; }
    if (tid < 16) sB2[tid] = b_e2[tid];
    if (tid == 0) { sScal[0] = b_a2[0]; sScal[1] = b_c2[0]; }
    if (tid < 32) sIdx[tid] = nbhd[bn*Jj + tid];
    __syncthreads();

    int w = tid >> 5, lane = tid & 31;
    int qq = lane >> 3, s = lane & 7;
    int j = w*4 + qq;
    int idx = sIdx[j];
    long krow = ((long)(bB*Nn + idx)*4) * HP;

    // rel_enc: lanes s=0..3 -> sin(x/2^s), s=4..7 -> cos(x/2^(s-4))
    float dx = coors[bn*3+0] - coors[(bB*Nn+idx)*3+0];
    float dy = coors[bn*3+1] - coors[(bB*Nn+idx)*3+1];
    float dz = coors[bn*3+2] - coors[(bB*Nn+idx)*3+2];
    float x = dx*dx + dy*dy + dz*dz;
    float xs = x / (float)(1 << (s & 3));
    float sv = sinf(xs), cv = cosf(xs);
    float myre = (s < 4) ? sv : cv;
    float re[9];
    #pragma unroll
    for (int f = 0; f < 8; f++) re[f] = __shfl_sync(0xffffffffu, myre, f, 8);
    re[8] = x;

    float acc[4][16];
    #pragma unroll
    for (int h = 0; h < 4; h++)
        #pragma unroll
        for (int t = 0; t < 16; t++) acc[h][t] = 0.f;

    #pragma unroll 1
    for (int r = 0; r < 9; r++) {
        int i0 = (s + 8*r) * 4;
        // r1 chunk
        float4 r1v = *(float4*)&sB1[i0];
        #pragma unroll
        for (int f = 0; f < 9; f++) {
            float4 wv = *(float4*)&sWr[f*HP + i0];
            r1v.x += re[f]*wv.x; r1v.y += re[f]*wv.y;
            r1v.z += re[f]*wv.z; r1v.w += re[f]*wv.w;
        }
        // h chunks, 4 heads
        float4 hv[4];
        #pragma unroll
        for (int h = 0; h < 4; h++) {
            float4 q4 = *(float4*)&sQ1[h*HP + i0];
            float4 k4 = *(const float4*)&k1[krow + h*HP + i0];
            hv[h].x = fmaxf(q4.x + k4.x + r1v.x, 0.f);
            hv[h].y = fmaxf(q4.y + k4.y + r1v.y, 0.f);
            hv[h].z = fmaxf(q4.z + k4.z + r1v.z, 0.f);
            hv[h].w = fmaxf(q4.w + k4.w + r1v.w, 0.f);
        }
        // layer2: W2 row chunk loaded once, used by all 4 heads
        #pragma unroll
        for (int t = 0; t < 16; t++) {
            float4 wv = *(float4*)&sW2t[t*W2S + i0];
            #pragma unroll
            for (int h = 0; h < 4; h++)
                acc[h][t] += hv[h].x*wv.x + hv[h].y*wv.y
                           + hv[h].z*wv.z + hv[h].w*wv.w;
        }
    }

    // butterfly reduce over 8-lane group
    #pragma unroll
    for (int h = 0; h < 4; h++)
        #pragma unroll
        for (int t = 0; t < 16; t++) {
            float v = acc[h][t];
            v += __shfl_xor_sync(0xffffffffu, v, 1);
            v += __shfl_xor_sync(0xffffffffu, v, 2);
            v += __shfl_xor_sync(0xffffffffu, v, 4);
            acc[h][t] = v;
        }

    // branch task per lane: h = s>>1, br = s&1
    int hh = s >> 1, br = s & 1;
    float mv[16];
    #pragma unroll
    for (int t = 0; t < 16; t++) {
        float v01 = (hh & 1) ? acc[1][t] : acc[0][t];
        float v23 = (hh & 1) ? acc[3][t] : acc[2][t];
        float v = (hh & 2) ? v23 : v01;
        mv[t] = fmaxf(v + sB2[t], 0.f);
    }
    const float* w1 = br ? sC1 : sA1;
    const float* w2 = br ? sC2 : sA2;
    const float* bb = br ? sBc : sBa;
    float bacc = 0.f;
    #pragma unroll 4
    for (int u4 = 0; u4 < 16; u4++) {
        float4 hv = *(float4*)&bb[u4*4];
        #pragma unroll
        for (int t = 0; t < 16; t++) {
            float4 wv = *(float4*)&w1[t*64 + u4*4];
            hv.x += mv[t]*wv.x; hv.y += mv[t]*wv.y;
            hv.z += mv[t]*wv.z; hv.w += mv[t]*wv.w;
        }
        float4 w2v = *(float4*)&w2[u4*4];
        bacc += fmaxf(hv.x,0.f)*w2v.x + fmaxf(hv.y,0.f)*w2v.y
              + fmaxf(hv.z,0.f)*w2v.z + fmaxf(hv.w,0.f)*w2v.w;
    }
    long e = ((long)(bB*Hh + hh)*Nn + nn)*Jj + j;
    float val = bacc + (br ? sScal[1] : sScal[0]);
    (br ? cwo : simo)[e] = val;
}

// ---------------- softmax over j, out = attn@v_nb, coors_out ----------------
__global__ void attend_kernel(const float* __restrict__ qkv,
                              const float* __restrict__ simi, const float* __restrict__ cwi,
                              const int* __restrict__ nbhd, const float* __restrict__ basis,
                              float* __restrict__ outh, float* __restrict__ coors_out)
{
    int bn = blockIdx.x;
    int b = bn / Nn, n = bn % Nn;
    int w = threadIdx.x >> 5, lane = threadIdx.x & 31;
    int idx = nbhd[bn*Jj + lane];

    float s = simi[((long)((b*Hh + w)*Nn + n))*Jj + lane];
    float mx = s;
    #pragma unroll
    for (int o = 16; o; o >>= 1) mx = fmaxf(mx, __shfl_xor_sync(0xffffffffu, mx, o));
    float e = expf(s - mx);
    float sum = e;
    #pragma unroll
    for (int o = 16; o; o >>= 1) sum += __shfl_xor_sync(0xffffffffu, sum, o);
    float attn = e / sum;

    float acc0 = 0.f, acc1 = 0.f;
    #pragma unroll
    for (int j = 0; j < Jj; j++) {
        float a = __shfl_sync(0xffffffffu, attn, j);
        int ij  = __shfl_sync(0xffffffffu, idx,  j);
        const float* vr = qkv + (long)(b*Nn + ij)*QKVC + 2*Hh*DHd + w*DHd;
        acc0 += a * vr[lane];
        acc1 += a * vr[lane + 32];
    }
    outh[(long)bn*Dd + w*DHd + lane]      = acc0;
    outh[(long)bn*Dd + w*DHd + lane + 32] = acc1;

    if (w == 0) {
        float cwt = 0.f;
        #pragma unroll
        for (int hh = 0; hh < Hh; hh++)
            cwt += cwi[((long)((b*Hh + hh)*Nn + n))*Jj + lane];
        const float* brow = basis + ((long)(b*Nn + n)*Nn + idx)*3;
        float cx = cwt*brow[0], cy = cwt*brow[1], cz = cwt*brow[2];
        #pragma unroll
        for (int o = 16; o; o >>= 1) {
            cx += __shfl_xor_sync(0xffffffffu, cx, o);
            cy += __shfl_xor_sync(0xffffffffu, cy, o);
            cz += __shfl_xor_sync(0xffffffffu, cz, o);
        }
        if (lane == 0) {
            coors_out[bn*3+0] = cx;
            coors_out[bn*3+1] = cy;
            coors_out[bn*3+2] = cz;
        }
    }
}

// ---------------- launch ----------------
extern "C" void kernel_launch(void* const* d_in, const int* in_sizes, int n_in,
                              void* d_out, int out_size)
{
    const float* feats  = (const float*)d_in[0];
    const float* coors  = (const float*)d_in[1];
    const float* basis  = (const float*)d_in[2];
    const int*   nbhd   = (const int*)  d_in[3];
    const float* w_qkv  = (const float*)d_in[4];
    const float* w_out  = (const float*)d_in[5];
    const float* b_out  = (const float*)d_in[6];
    const float* w_e1   = (const float*)d_in[7];
    const float* b_e1   = (const float*)d_in[8];
    const float* w_e2   = (const float*)d_in[9];
    const float* b_e2   = (const float*)d_in[10];
    const float* w_a1   = (const float*)d_in[11];
    const float* b_a1   = (const float*)d_in[12];
    const float* w_a2   = (const float*)d_in[13];
    const float* b_a2   = (const float*)d_in[14];
    const float* w_c1   = (const float*)d_in[15];
    const float* b_c1   = (const float*)d_in[16];
    const float* w_c2   = (const float*)d_in[17];
    const float* b_c2   = (const float*)d_in[18];

    float* out       = (float*)d_out;
    float* coors_out = out + (long)Bq*Nn*Dd;

    void* p;
    cudaGetSymbolAddress(&p, g_qkv);  float* qkv  = (float*)p;
    cudaGetSymbolAddress(&p, g_q1);   float* q1   = (float*)p;
    cudaGetSymbolAddress(&p, g_k1);   float* k1   = (float*)p;
    cudaGetSymbolAddress(&p, g_sim);  float* simv = (float*)p;
    cudaGetSymbolAddress(&p, g_cw);   float* cwv  = (float*)p;
    cudaGetSymbolAddress(&p, g_outh); float* outh = (float*)p;

    // 1) qkv = feats @ w_qkv
    gemm_tile<<<dim3(QKVC/64, (Bq*Nn)/64), 256>>>(feats, w_qkv, nullptr, qkv,
                                                  Bq*Nn, QKVC, Dd);

    // 2) q1/k1 tables
    const int smemQK = (64*HP*2 + 16*256*2) * 4;
    cudaFuncSetAttribute(qk1_kernel, cudaFuncAttributeMaxDynamicSharedMemorySize, smemQK);
    qk1_kernel<<<256, 256, smemQK>>>(qkv, w_e1, q1, k1);

    // 3) edge_flat
    const int smemE = (9*HP + 16*W2S + HP + 4*HP + 1024 + 1024 + 64*4 + 16 + 4 + 32) * 4;
    cudaFuncSetAttribute(edge_flat, cudaFuncAttributeMaxDynamicSharedMemorySize, smemE);
    edge_flat<<<NODES, 256, smemE>>>(q1, k1, coors, nbhd,
        w_e1, b_e1, w_e2, b_e2, w_a1, b_a1, w_a2, b_a2, w_c1, b_c1, w_c2, b_c2,
        simv, cwv);

    // 4) softmax + v-gather + coors einsum
    attend_kernel<<<Bq*Nn, 128>>>(qkv, simv, cwv, nbhd, basis, outh, coors_out);

    // 5) out = outh @ w_out + b_out
    gemm_tile<<<dim3(Dd/64, (Bq*Nn)/64), 256>>>(outh, w_out, b_out, out,
                                                Bq*Nn, Dd, Dd);
}